// round 1
// baseline (speedup 1.0000x reference)
#include <cuda_runtime.h>
#include <cuda_bf16.h>
#include <cstdint>

// Problem constants
#define D      64
#define K      1024
#define HW     4096        // 64*64
#define NROWS  131072      // 32*64*64
#define MT     128         // rows per block
#define NT     128         // codes per tile
#define XPITCH 132         // padded pitch for xs to kill bank conflicts in epilogue

// Output layout (concatenated, float32): quantized_out (b,c,h,w), loss (b,h,w,c), idx (b,h,w)
#define LOFF   8388608
#define IOFF   16777216

// Scratch (no cudaMalloc allowed)
__device__ float g_eT[D * K];   // embedding transposed [d][k]
__device__ float g_e2[K];       // ||e_k||^2

// ---------------------------------------------------------------------------
// Prep: transpose embedding + row norms. Tiny (256 KB), runs in a few us.
// ---------------------------------------------------------------------------
__global__ void vq_prep_kernel(const float* __restrict__ emb) {
    int k = blockIdx.x * blockDim.x + threadIdx.x;
    if (k < K) {
        float s = 0.0f;
#pragma unroll
        for (int d = 0; d < D; ++d) {
            float v = emb[k * D + d];
            g_eT[d * K + k] = v;
            s = fmaf(v, v, s);
        }
        g_e2[k] = s;
    }
}

// ---------------------------------------------------------------------------
// Main kernel: distances + argmin + all three outputs, one block per 128 rows.
// GEMM tiling: 128m x 128n per block, 256 threads, 8m x 8n per thread,
// f32x2 packed FMA (pairs along m).
// ---------------------------------------------------------------------------
extern __shared__ float sm[];

__global__ __launch_bounds__(256) void vq_main_kernel(
    const float* __restrict__ x,     // [b, c, h, w] fp32
    const float* __restrict__ emb,   // [K, D] fp32
    float* __restrict__ out)
{
    float* xs = sm;                       // [64][XPITCH]  (x tile, transposed)
    float* es = sm + D * XPITCH;          // [64][128]     (e tile, d-major); reused as reduce scratch
    __shared__ float rs[MT];              // row sums ||x||^2
    __shared__ float e2s[NT];             // code norms for current tile
    __shared__ int   idxRow[MT];          // final argmin per row

    const int tid = threadIdx.x;
    const int p0  = blockIdx.x * MT;      // first global row of this block
    const int b   = p0 >> 12;             // p0 / 4096
    const int s0  = p0 & 4095;            // spatial offset within image
    const float* xbase = x + (size_t)b * 64 * HW + s0;

    // ---- load x tile: for each channel d, 128 contiguous spatial floats ----
#pragma unroll
    for (int i = 0; i < 32; ++i) {
        int idx = tid + i * 256;
        int d = idx >> 7, m = idx & 127;
        xs[d * XPITCH + m] = xbase[d * HW + m];
    }
    __syncthreads();

    // ---- per-row ||x||^2 (order benign: uniform shift per row) ----
    if (tid < MT) {
        float s = 0.0f;
#pragma unroll
        for (int d = 0; d < D; ++d) {
            float v = xs[d * XPITCH + tid];
            s = fmaf(v, v, s);
        }
        rs[tid] = s;
    }

    const int tx = tid & 15;   // n-group: codes tx*8 .. tx*8+7
    const int ty = tid >> 4;   // m-group: rows  ty*8 .. ty*8+7

    float bestv[8];
    int   besti[8];
#pragma unroll
    for (int i = 0; i < 8; ++i) { bestv[i] = 3.4e38f; besti[i] = 0; }

    for (int nt = 0; nt < K / NT; ++nt) {
        __syncthreads();   // protect es before overwrite (also publishes rs on first iter... see below)
        // ---- load e tile [d][n] (coalesced from pre-transposed g_eT) ----
        const float* eTt = g_eT + nt * NT;
#pragma unroll
        for (int i = 0; i < 32; ++i) {
            int idx = tid + i * 256;
            int d = idx >> 7, n = idx & 127;
            es[d * NT + n] = eTt[d * K + n];
        }
        if (tid < NT) e2s[tid] = g_e2[nt * NT + tid];
        __syncthreads();   // es, e2s (and rs) visible

        // ---- 8x8 register tile, f32x2 packed along m ----
        unsigned long long acc[4][8];
#pragma unroll
        for (int mp = 0; mp < 4; ++mp)
#pragma unroll
            for (int j = 0; j < 8; ++j) acc[mp][j] = 0ULL;

#pragma unroll 16
        for (int d = 0; d < D; ++d) {
            const float* xrow = xs + d * XPITCH + ty * 8;
            ulonglong2 xA = *(const ulonglong2*)(xrow);       // rows (0,1),(2,3)
            ulonglong2 xB = *(const ulonglong2*)(xrow + 4);   // rows (4,5),(6,7)
            unsigned long long ax[4] = { xA.x, xA.y, xB.x, xB.y };

            const float4* ep = (const float4*)(es + d * NT + tx * 8);
            float4 e0 = ep[0], e1 = ep[1];
            float ev[8] = { e0.x, e0.y, e0.z, e0.w, e1.x, e1.y, e1.z, e1.w };
#pragma unroll
            for (int j = 0; j < 8; ++j) {
                unsigned long long bv;
                asm("mov.b64 %0, {%1, %1};" : "=l"(bv) : "f"(ev[j]));
#pragma unroll
                for (int mp = 0; mp < 4; ++mp)
                    asm("fma.rn.f32x2 %0, %1, %2, %0;"
                        : "+l"(acc[mp][j]) : "l"(ax[mp]), "l"(bv));
            }
        }

        // ---- distances + running argmin (ascending n, strict < keeps first) ----
#pragma unroll
        for (int j = 0; j < 8; ++j) {
            int n = nt * NT + tx * 8 + j;
            float e2 = e2s[tx * 8 + j];
#pragma unroll
            for (int mp = 0; mp < 4; ++mp) {
                float2 dv = *(float2*)&acc[mp][j];
                // reference association: (||x||^2 + ||e||^2) - 2*dot, one rounding each
                float t0 = rs[ty * 8 + 2 * mp]     + e2;
                float t1 = rs[ty * 8 + 2 * mp + 1] + e2;
                float d0 = fmaf(dv.x, -2.0f, t0);
                float d1 = fmaf(dv.y, -2.0f, t1);
                if (d0 < bestv[2 * mp])     { bestv[2 * mp]     = d0; besti[2 * mp]     = n; }
                if (d1 < bestv[2 * mp + 1]) { bestv[2 * mp + 1] = d1; besti[2 * mp + 1] = n; }
            }
        }
    }

    // ---- cross-thread argmin reduce (reuse es as scratch) ----
    __syncthreads();
    float* redv = es;                 // [128][16]
    int*   redi = (int*)(es + 2048);  // [128][16]
#pragma unroll
    for (int i = 0; i < 8; ++i) {
        int m = ty * 8 + i;
        redv[m * 16 + tx] = bestv[i];
        redi[m * 16 + tx] = besti[i];
    }
    __syncthreads();
    if (tid < MT) {
        float bv = redv[tid * 16];
        int   bi = redi[tid * 16];
#pragma unroll
        for (int t = 1; t < 16; ++t) {
            float v = redv[tid * 16 + t];
            int   ii = redi[tid * 16 + t];
            if (v < bv || (v == bv && ii < bi)) { bv = v; bi = ii; }
        }
        idxRow[tid] = bi;
        out[IOFF + p0 + tid] = (float)bi;   // idx as float (output dtype f32)
    }
    __syncthreads();

    // ---- loss (b,h,w,c): coalesced, 64 contiguous floats per row ----
#pragma unroll
    for (int i = 0; i < 32; ++i) {
        int idx = tid + i * 256;
        int m = idx >> 6, c = idx & 63;
        float xv = xs[c * XPITCH + m];
        float ev = emb[idxRow[m] * D + c];
        float df = ev - xv;                 // (quantized - x), one rounding
        float t  = df * df;
        out[LOFF + (size_t)(p0 + m) * 64 + c] = t + 0.25f * t;  // == round(1.25*t)
    }

    // ---- quantized_out (b,c,h,w): per channel, 128 contiguous floats ----
#pragma unroll
    for (int i = 0; i < 32; ++i) {
        int idx = tid + i * 256;
        int c = idx >> 7, m = idx & 127;
        float xv = xs[c * XPITCH + m];
        float ev = emb[idxRow[m] * D + c];
        // straight-through: x + (q - x), NOT q (last-ulp fidelity to reference)
        out[(size_t)(b * 64 + c) * HW + s0 + m] = xv + (ev - xv);
    }
}

// ---------------------------------------------------------------------------
extern "C" void kernel_launch(void* const* d_in, const int* in_sizes, int n_in,
                              void* d_out, int out_size)
{
    const float* x_in = (const float*)d_in[0];   // inputs  [32,64,64,64]
    const float* emb  = (const float*)d_in[1];   // embedding [1024,64]
    float* out = (float*)d_out;

    static bool attr_set = false;
    size_t smem_bytes = (size_t)(D * XPITCH + D * NT) * sizeof(float);  // ~66.5 KB
    if (!attr_set) {
        cudaFuncSetAttribute(vq_main_kernel,
                             cudaFuncAttributeMaxDynamicSharedMemorySize,
                             (int)smem_bytes);
        attr_set = true;
    }

    vq_prep_kernel<<<4, 256>>>(emb);
    vq_main_kernel<<<NROWS / MT, 256, smem_bytes>>>(x_in, emb, out);
}

// round 2
// speedup vs baseline: 1.0732x; 1.0732x over previous
#include <cuda_runtime.h>
#include <cuda_bf16.h>
#include <cstdint>

// Problem constants
#define D      64
#define K      1024
#define HW     4096        // 64*64
#define NROWS  131072      // 32*64*64
#define MT     128         // rows per block
#define NT     128         // codes per tile
#define XPITCH 132         // padded pitch for xs to kill bank conflicts in epilogue

// Output layout (concatenated, float32): quantized_out (b,c,h,w), loss (b,h,w,c), idx (b,h,w)
#define LOFF   8388608
#define IOFF   16777216

// Scratch (no cudaMalloc allowed)
__device__ float g_eT[D * K];   // embedding transposed [d][k]
__device__ float g_e2[K];       // ||e_k||^2

// ---------------------------------------------------------------------------
// Prep: transpose embedding + row norms. Tiny (256 KB), runs in a few us.
// ---------------------------------------------------------------------------
__global__ void vq_prep_kernel(const float* __restrict__ emb) {
    int k = blockIdx.x * blockDim.x + threadIdx.x;
    if (k < K) {
        float s = 0.0f;
#pragma unroll
        for (int d = 0; d < D; ++d) {
            float v = emb[k * D + d];
            g_eT[d * K + k] = v;
            s = fmaf(v, v, s);
        }
        g_e2[k] = s;
    }
}

// ---------------------------------------------------------------------------
// Main kernel: distances + argmin + all three outputs, one block per 128 rows.
// GEMM tiling: 128m x 128n per block, 256 threads, 8m x 8n per thread,
// f32x2 packed FMA (pairs along m).
// __launch_bounds__(256, 2): cap at 128 regs so 2 CTAs (16 warps) fit per SM.
// ---------------------------------------------------------------------------
extern __shared__ float sm[];

__global__ __launch_bounds__(256, 2) void vq_main_kernel(
    const float* __restrict__ x,     // [b, c, h, w] fp32
    const float* __restrict__ emb,   // [K, D] fp32
    float* __restrict__ out)
{
    float* xs = sm;                       // [64][XPITCH]  (x tile, transposed)
    float* es = sm + D * XPITCH;          // [64][128]     (e tile, d-major); reused as reduce scratch
    __shared__ float rs[MT];              // row sums ||x||^2
    __shared__ float e2s[NT];             // code norms for current tile
    __shared__ int   idxRow[MT];          // final argmin per row

    const int tid = threadIdx.x;
    const int p0  = blockIdx.x * MT;      // first global row of this block
    const int b   = p0 >> 12;             // p0 / 4096
    const int s0  = p0 & 4095;            // spatial offset within image
    const float* xbase = x + (size_t)b * 64 * HW + s0;

    // ---- load x tile: for each channel d, 128 contiguous spatial floats ----
#pragma unroll
    for (int i = 0; i < 32; ++i) {
        int idx = tid + i * 256;
        int d = idx >> 7, m = idx & 127;
        xs[d * XPITCH + m] = xbase[d * HW + m];
    }
    __syncthreads();

    // ---- per-row ||x||^2 (order benign: uniform shift per row) ----
    if (tid < MT) {
        float s = 0.0f;
#pragma unroll
        for (int d = 0; d < D; ++d) {
            float v = xs[d * XPITCH + tid];
            s = fmaf(v, v, s);
        }
        rs[tid] = s;
    }

    const int tx = tid & 15;   // n-group: codes tx*8 .. tx*8+7
    const int ty = tid >> 4;   // m-group: rows  ty*8 .. ty*8+7

    float bestv[8];
    int   besti[8];
#pragma unroll
    for (int i = 0; i < 8; ++i) { bestv[i] = 3.4e38f; besti[i] = 0; }

    for (int nt = 0; nt < K / NT; ++nt) {
        __syncthreads();   // protect es before overwrite (also publishes rs on first iter)
        // ---- load e tile [d][n] (coalesced from pre-transposed g_eT) ----
        const float* eTt = g_eT + nt * NT;
#pragma unroll
        for (int i = 0; i < 32; ++i) {
            int idx = tid + i * 256;
            int d = idx >> 7, n = idx & 127;
            es[d * NT + n] = eTt[d * K + n];
        }
        if (tid < NT) e2s[tid] = g_e2[nt * NT + tid];
        __syncthreads();   // es, e2s (and rs) visible

        // ---- 8x8 register tile, f32x2 packed along m ----
        unsigned long long acc[4][8];
#pragma unroll
        for (int mp = 0; mp < 4; ++mp)
#pragma unroll
            for (int j = 0; j < 8; ++j) acc[mp][j] = 0ULL;

#pragma unroll 4
        for (int d = 0; d < D; ++d) {
            const float* xrow = xs + d * XPITCH + ty * 8;
            ulonglong2 xA = *(const ulonglong2*)(xrow);       // rows (0,1),(2,3)
            ulonglong2 xB = *(const ulonglong2*)(xrow + 4);   // rows (4,5),(6,7)
            unsigned long long ax[4] = { xA.x, xA.y, xB.x, xB.y };

            const float4* ep = (const float4*)(es + d * NT + tx * 8);
            float4 e0 = ep[0], e1 = ep[1];
            float ev[8] = { e0.x, e0.y, e0.z, e0.w, e1.x, e1.y, e1.z, e1.w };
#pragma unroll
            for (int j = 0; j < 8; ++j) {
                unsigned long long bv;
                asm("mov.b64 %0, {%1, %1};" : "=l"(bv) : "f"(ev[j]));
#pragma unroll
                for (int mp = 0; mp < 4; ++mp)
                    asm("fma.rn.f32x2 %0, %1, %2, %0;"
                        : "+l"(acc[mp][j]) : "l"(ax[mp]), "l"(bv));
            }
        }

        // ---- distances + running argmin (ascending n, strict < keeps first) ----
#pragma unroll
        for (int j = 0; j < 8; ++j) {
            int n = nt * NT + tx * 8 + j;
            float e2 = e2s[tx * 8 + j];
#pragma unroll
            for (int mp = 0; mp < 4; ++mp) {
                float2 dv = *(float2*)&acc[mp][j];
                // reference association: (||x||^2 + ||e||^2) - 2*dot, one rounding each
                float t0 = rs[ty * 8 + 2 * mp]     + e2;
                float t1 = rs[ty * 8 + 2 * mp + 1] + e2;
                float d0 = fmaf(dv.x, -2.0f, t0);
                float d1 = fmaf(dv.y, -2.0f, t1);
                if (d0 < bestv[2 * mp])     { bestv[2 * mp]     = d0; besti[2 * mp]     = n; }
                if (d1 < bestv[2 * mp + 1]) { bestv[2 * mp + 1] = d1; besti[2 * mp + 1] = n; }
            }
        }
    }

    // ---- cross-thread argmin reduce (reuse es as scratch) ----
    __syncthreads();
    float* redv = es;                 // [128][16]
    int*   redi = (int*)(es + 2048);  // [128][16]
#pragma unroll
    for (int i = 0; i < 8; ++i) {
        int m = ty * 8 + i;
        redv[m * 16 + tx] = bestv[i];
        redi[m * 16 + tx] = besti[i];
    }
    __syncthreads();
    if (tid < MT) {
        float bv = redv[tid * 16];
        int   bi = redi[tid * 16];
#pragma unroll
        for (int t = 1; t < 16; ++t) {
            float v = redv[tid * 16 + t];
            int   ii = redi[tid * 16 + t];
            if (v < bv || (v == bv && ii < bi)) { bv = v; bi = ii; }
        }
        idxRow[tid] = bi;
        out[IOFF + p0 + tid] = (float)bi;   // idx as float (output dtype f32)
    }
    __syncthreads();

    // ---- loss (b,h,w,c): coalesced, 64 contiguous floats per row ----
#pragma unroll
    for (int i = 0; i < 32; ++i) {
        int idx = tid + i * 256;
        int m = idx >> 6, c = idx & 63;
        float xv = xs[c * XPITCH + m];
        float ev = emb[idxRow[m] * D + c];
        float df = ev - xv;                 // (quantized - x), one rounding
        float t  = df * df;
        out[LOFF + (size_t)(p0 + m) * 64 + c] = t + 0.25f * t;  // == round(1.25*t)
    }

    // ---- quantized_out (b,c,h,w): per channel, 128 contiguous floats ----
#pragma unroll
    for (int i = 0; i < 32; ++i) {
        int idx = tid + i * 256;
        int c = idx >> 7, m = idx & 127;
        float xv = xs[c * XPITCH + m];
        float ev = emb[idxRow[m] * D + c];
        // straight-through: x + (q - x), NOT q (last-ulp fidelity to reference)
        out[(size_t)(b * 64 + c) * HW + s0 + m] = xv + (ev - xv);
    }
}

// ---------------------------------------------------------------------------
extern "C" void kernel_launch(void* const* d_in, const int* in_sizes, int n_in,
                              void* d_out, int out_size)
{
    const float* x_in = (const float*)d_in[0];   // inputs  [32,64,64,64]
    const float* emb  = (const float*)d_in[1];   // embedding [1024,64]
    float* out = (float*)d_out;

    static bool attr_set = false;
    size_t smem_bytes = (size_t)(D * XPITCH + D * NT) * sizeof(float);  // ~66.5 KB
    if (!attr_set) {
        cudaFuncSetAttribute(vq_main_kernel,
                             cudaFuncAttributeMaxDynamicSharedMemorySize,
                             (int)smem_bytes);
        attr_set = true;
    }

    vq_prep_kernel<<<4, 256>>>(emb);
    vq_main_kernel<<<NROWS / MT, 256, smem_bytes>>>(x_in, emb, out);
}